// round 3
// baseline (speedup 1.0000x reference)
#include <cuda_runtime.h>
#include <cstdint>
#include <cstddef>

#define B_   64
#define S_   256
#define D_   512
#define H_   1024
#define G4_  4096
#define NBLK 128
#define KC   128

// ---------------- scratch (device globals; no allocation allowed) ----------------
__device__ __align__(128) float g_gx[67108864];   // [S][4H][B]  268MB (reused for both layers)
__device__ __align__(128) float g_h1[16777216];   // [S][H][B]   67MB
__device__ __align__(128) float g_h2[16777216];   // [S][H][B]   67MB
__device__ int g_flags[256];

// ---------------- f32x2 helpers ----------------
__device__ __forceinline__ unsigned long long pk2(float x, float y) {
    unsigned long long r;
    asm("mov.b64 %0, {%1, %2};" : "=l"(r) : "f"(x), "f"(y));
    return r;
}
__device__ __forceinline__ float2 upk2(unsigned long long v) {
    float2 r;
    asm("mov.b64 {%0, %1}, %2;" : "=f"(r.x), "=f"(r.y) : "l"(v));
    return r;
}
__device__ __forceinline__ void fma2(unsigned long long& d, unsigned long long a, unsigned long long b) {
    asm("fma.rn.f32x2 %0, %1, %2, %0;" : "+l"(d) : "l"(a), "l"(b));
}

__device__ __forceinline__ float sigf(float x)   { return 1.f / (1.f + __expf(-x)); }
__device__ __forceinline__ float tanhf_(float x) { return 2.f / (1.f + __expf(-2.f * x)) - 1.f; }
__device__ __forceinline__ float actf(float x)   { return x > 0.f ? 1.f / (1.f + __expf(-x)) : 0.5f; }

// ---------------- input GEMM: gx[s][g][b] = sum_d W[g,d]*X[d,(s,b)] + bias ----------------
// MODEB=0: X = x laid out [B][S][D]    (layer 0 input)
// MODEB=1: X = h1 laid out [S][K][B]   (layer 1 input)
template<int KDIM, int MODEB>
__global__ void __launch_bounds__(256)
gemm_gx_kernel(const float* __restrict__ W, const float* __restrict__ X,
               const float* __restrict__ bA, const float* __restrict__ bB,
               float* __restrict__ gx)
{
    __shared__ float As[16][132];   // [k][g], padded
    __shared__ float Bs[16][68];    // [k][b], padded

    const int s  = blockIdx.y;
    const int gt = blockIdx.x;      // 128-row g tile
    const int t  = threadIdx.x;
    const int tx = t & 15, ty = t >> 4;
    const int b0 = tx * 4, g0 = ty * 8;

    unsigned long long acc[8][2];
#pragma unroll
    for (int i = 0; i < 8; ++i) { acc[i][0] = 0ull; acc[i][1] = 0ull; }

    const int rA = t >> 1;
    const int cA = (t & 1) * 8;

    for (int kt = 0; kt < KDIM / 16; ++kt) {
        // A tile: W rows [gt*128, gt*128+128), cols [kt*16, kt*16+16)
        {
            const float* src = W + (size_t)(gt * 128 + rA) * KDIM + kt * 16 + cA;
            float4 a0 = *(const float4*)src;
            float4 a1 = *(const float4*)(src + 4);
            As[cA + 0][rA] = a0.x; As[cA + 1][rA] = a0.y; As[cA + 2][rA] = a0.z; As[cA + 3][rA] = a0.w;
            As[cA + 4][rA] = a1.x; As[cA + 5][rA] = a1.y; As[cA + 6][rA] = a1.z; As[cA + 7][rA] = a1.w;
        }
        // B tile
        if (MODEB == 0) {
            int bb = t >> 2, q = (t & 3) * 4;
            const float* src = X + ((size_t)bb * S_ + s) * KDIM + kt * 16 + q;
            float4 v = *(const float4*)src;
            Bs[q + 0][bb] = v.x; Bs[q + 1][bb] = v.y; Bs[q + 2][bb] = v.z; Bs[q + 3][bb] = v.w;
        } else {
            int dk = t >> 4, bb = (t & 15) * 4;
            float4 v = *(const float4*)(X + ((size_t)s * KDIM + kt * 16 + dk) * B_ + bb);
            *(float4*)&Bs[dk][bb] = v;
        }
        __syncthreads();

#pragma unroll
        for (int k = 0; k < 16; ++k) {
            float4 a0 = *(const float4*)&As[k][g0];
            float4 a1 = *(const float4*)&As[k][g0 + 4];
            float4 bv = *(const float4*)&Bs[k][b0];
            unsigned long long bp0 = pk2(bv.x, bv.y);
            unsigned long long bp1 = pk2(bv.z, bv.w);
            unsigned long long av;
            av = pk2(a0.x, a0.x); fma2(acc[0][0], av, bp0); fma2(acc[0][1], av, bp1);
            av = pk2(a0.y, a0.y); fma2(acc[1][0], av, bp0); fma2(acc[1][1], av, bp1);
            av = pk2(a0.z, a0.z); fma2(acc[2][0], av, bp0); fma2(acc[2][1], av, bp1);
            av = pk2(a0.w, a0.w); fma2(acc[3][0], av, bp0); fma2(acc[3][1], av, bp1);
            av = pk2(a1.x, a1.x); fma2(acc[4][0], av, bp0); fma2(acc[4][1], av, bp1);
            av = pk2(a1.y, a1.y); fma2(acc[5][0], av, bp0); fma2(acc[5][1], av, bp1);
            av = pk2(a1.z, a1.z); fma2(acc[6][0], av, bp0); fma2(acc[6][1], av, bp1);
            av = pk2(a1.w, a1.w); fma2(acc[7][0], av, bp0); fma2(acc[7][1], av, bp1);
        }
        __syncthreads();
    }

#pragma unroll
    for (int gi = 0; gi < 8; ++gi) {
        int g = gt * 128 + g0 + gi;
        float bias = bA[g] + bB[g];
        float2 p0 = upk2(acc[gi][0]);
        float2 p1 = upk2(acc[gi][1]);
        float4 o = make_float4(p0.x + bias, p0.y + bias, p1.x + bias, p1.y + bias);
        *(float4*)(gx + ((size_t)s * G4_ + g) * B_ + b0) = o;
    }
}

// ---------------- flag reset (before each recurrence) ----------------
__global__ void reset_flags_kernel() { g_flags[threadIdx.x] = 0; }

// ---------------- persistent recurrence ----------------
// 128 blocks x 256 threads. WARP w owns h-column j = blk*8 + w (weight reads are
// warp-uniform -> smem broadcast, no bank conflicts). LANE l owns batch pair b=2l..2l+1.
// smem: Wsi [8jj][1024k][4 gates] = 128KB  +  Hs double buffer 2x[128k][64b] = 64KB
__global__ void __launch_bounds__(256, 1)
recur_kernel(const float* __restrict__ gx, const float* __restrict__ Whh,
             float* __restrict__ hseq)
{
    extern __shared__ float sm[];
    float* Wsi = sm;                 // 32768 floats
    float* Hs  = sm + 8 * H_ * 4;    // 2 * 8192 floats

    const int tid  = threadIdx.x;
    const int blk  = blockIdx.x;
    const int jj   = tid >> 5;       // warp id 0..7 -> h column within block
    const int lane = tid & 31;
    const int b0   = lane * 2;
    const int j    = blk * 8 + jj;

    // Build gate-interleaved weight slice: Wsi[(wj*1024 + k)*4 + gate] = Whh[gate*H + row][k]
    for (int idx = tid; idx < 8 * H_; idx += 256) {
        int wj = idx >> 10;
        int k  = idx & 1023;
        int row = blk * 8 + wj;
        float wi = Whh[((size_t)(0 * H_ + row)) * H_ + k];
        float wf = Whh[((size_t)(1 * H_ + row)) * H_ + k];
        float wg = Whh[((size_t)(2 * H_ + row)) * H_ + k];
        float wo = Whh[((size_t)(3 * H_ + row)) * H_ + k];
        float* d = Wsi + ((size_t)(wj << 10) + k) * 4;
        d[0] = wi; d[1] = wf; d[2] = wg; d[3] = wo;
    }
    __syncthreads();

    float c0 = 0.f, c1 = 0.f;
    volatile int* vf = (volatile int*)g_flags;
    const ulonglong2* wrow_base = (const ulonglong2*)(Wsi + (jj << 12));  // warp-uniform

    for (int t = 0; t < S_; ++t) {
        // gx accumulators (independent of flags -> issue early)
        size_t base = ((size_t)t * G4_ + j) * B_ + b0;
        float2 gi = *(const float2*)(gx + base);
        float2 gf = *(const float2*)(gx + base + (size_t)1 * H_ * B_);
        float2 gg = *(const float2*)(gx + base + (size_t)2 * H_ * B_);
        float2 go = *(const float2*)(gx + base + (size_t)3 * H_ * B_);
        unsigned long long aIF0 = pk2(gi.x, gf.x);
        unsigned long long aGO0 = pk2(gg.x, go.x);
        unsigned long long aIF1 = pk2(gi.y, gf.y);
        unsigned long long aGO1 = pk2(gg.y, go.y);

        if (t > 0) {
            if (tid == 0) { while (vf[t - 1] != NBLK) {} }
            __syncthreads();
            __threadfence();

            const float4* hp = (const float4*)(hseq + (size_t)(t - 1) * H_ * B_);
            float4 stage[8];
#pragma unroll
            for (int i = 0; i < 8; ++i) stage[i] = hp[tid + i * 256];

            for (int kc = 0; kc < H_ / KC; ++kc) {
                float* HsW = Hs + (kc & 1) * (KC * B_);
#pragma unroll
                for (int i = 0; i < 8; ++i) ((float4*)HsW)[tid + i * 256] = stage[i];
                __syncthreads();
                if (kc < H_ / KC - 1) {
#pragma unroll
                    for (int i = 0; i < 8; ++i) stage[i] = hp[(kc + 1) * 2048 + tid + i * 256];
                }
                const ulonglong2* wrow = wrow_base + kc * KC;
#pragma unroll 8
                for (int kk = 0; kk < KC; ++kk) {
                    ulonglong2 w = wrow[kk];                 // {(wi,wf),(wg,wo)} broadcast
                    float2 h2 = *(const float2*)(HsW + kk * B_ + b0);
                    unsigned long long h00 = pk2(h2.x, h2.x);
                    unsigned long long h11 = pk2(h2.y, h2.y);
                    fma2(aIF0, w.x, h00);
                    fma2(aGO0, w.y, h00);
                    fma2(aIF1, w.x, h11);
                    fma2(aGO1, w.y, h11);
                }
            }
        }

        // cell update + h write
        float2 vIF0 = upk2(aIF0), vGO0 = upk2(aGO0);
        float2 vIF1 = upk2(aIF1), vGO1 = upk2(aGO1);
        float i0 = sigf(vIF0.x), f0 = sigf(vIF0.y), g0v = tanhf_(vGO0.x), o0 = sigf(vGO0.y);
        float i1 = sigf(vIF1.x), f1 = sigf(vIF1.y), g1v = tanhf_(vGO1.x), o1 = sigf(vGO1.y);
        c0 = f0 * c0 + i0 * g0v;
        c1 = f1 * c1 + i1 * g1v;
        float h0  = o0 * tanhf_(c0);
        float h1v = o1 * tanhf_(c1);
        *(float2*)(hseq + ((size_t)t * H_ + j) * B_ + b0) = make_float2(h0, h1v);

        __threadfence();
        __syncthreads();
        if (tid == 0) atomicAdd(&g_flags[t], 1);
    }
}

// ---------------- fused transpose + sigmoid(relu) ----------------
__global__ void __launch_bounds__(256)
act_out_kernel(const float* __restrict__ h2, float* __restrict__ out)
{
    __shared__ float T[64][68];
    const int s = blockIdx.y, jt = blockIdx.x;
    const int t = threadIdx.x;
    {
        int jj0 = (t >> 4) * 4, bq = (t & 15) * 4;
#pragma unroll
        for (int r = 0; r < 4; ++r) {
            float4 v = *(const float4*)(h2 + ((size_t)s * H_ + jt * 64 + jj0 + r) * B_ + bq);
            *(float4*)&T[jj0 + r][bq] = v;
        }
    }
    __syncthreads();
    {
        int b0 = (t >> 4) * 4, jq = (t & 15) * 4;
#pragma unroll
        for (int i = 0; i < 4; ++i) {
            int b = b0 + i;
            float4 w;
            w.x = actf(T[jq + 0][b]);
            w.y = actf(T[jq + 1][b]);
            w.z = actf(T[jq + 2][b]);
            w.w = actf(T[jq + 3][b]);
            *(float4*)(out + (size_t)b * (S_ * H_) + (size_t)s * H_ + jt * 64 + jq) = w;
        }
    }
}

// ---------------- launcher ----------------
extern "C" void kernel_launch(void* const* d_in, const int* in_sizes, int n_in,
                              void* d_out, int out_size)
{
    const float* x    = (const float*)d_in[0];
    const float* Wih0 = (const float*)d_in[1];
    const float* Whh0 = (const float*)d_in[2];
    const float* bih0 = (const float*)d_in[3];
    const float* bhh0 = (const float*)d_in[4];
    const float* Wih1 = (const float*)d_in[5];
    const float* Whh1 = (const float*)d_in[6];
    const float* bih1 = (const float*)d_in[7];
    const float* bhh1 = (const float*)d_in[8];
    float* out = (float*)d_out;

    float *gx, *h1, *h2;
    cudaGetSymbolAddress((void**)&gx, g_gx);
    cudaGetSymbolAddress((void**)&h1, g_h1);
    cudaGetSymbolAddress((void**)&h2, g_h2);

    const int smem_rec = (8 * H_ * 4 + 2 * KC * B_) * (int)sizeof(float);  // 196608
    cudaFuncSetAttribute(recur_kernel, cudaFuncAttributeMaxDynamicSharedMemorySize, smem_rec);

    dim3 ggrid(G4_ / 128, S_);

    // Layer 0
    gemm_gx_kernel<D_, 0><<<ggrid, 256>>>(Wih0, x, bih0, bhh0, gx);
    reset_flags_kernel<<<1, 256>>>();
    recur_kernel<<<NBLK, 256, smem_rec>>>(gx, Whh0, h1);

    // Layer 1
    gemm_gx_kernel<H_, 1><<<ggrid, 256>>>(Wih1, h1, bih1, bhh1, gx);
    reset_flags_kernel<<<1, 256>>>();
    recur_kernel<<<NBLK, 256, smem_rec>>>(gx, Whh1, h2);

    // Epilogue
    dim3 agrid(H_ / 64, 256);
    act_out_kernel<<<agrid, 256>>>(h2, out);
}

// round 6
// speedup vs baseline: 1.7181x; 1.7181x over previous
#include <cuda_runtime.h>
#include <cuda_bf16.h>
#include <cstdint>
#include <cstddef>

#define B_   64
#define S_   256
#define D_   512
#define H_   1024
#define G4_  4096
#define NCTA 128
#define RSTR 66   // Rbuf row stride in floats (264B, multiple of 8B)

// ---------------- scratch (device globals) ----------------
__device__ __align__(128) float g_gx[67108864];            // [S][4H][B]
__device__ __align__(128) float g_h1[16777216];            // [S][H][B]
__device__ __align__(128) float g_h2[16777216];            // [S][H][B]
__device__ __align__(128) unsigned char g_WF[33554432];    // A fragments: [l][cta][w][mt][kt][lane][hi uint4|lo uint4]
__device__ __align__(128) unsigned char g_hfrag[524288];   // [buf][ktile 64][ntile 8][lane 32] uint4 {bhi0,bhi1,blo0,blo1}
__device__ int g_flags[256];

// ---------------- helpers ----------------
__device__ __forceinline__ unsigned long long pk2(float x, float y) {
    unsigned long long r; asm("mov.b64 %0, {%1, %2};" : "=l"(r) : "f"(x), "f"(y)); return r;
}
__device__ __forceinline__ float2 upk2(unsigned long long v) {
    float2 r; asm("mov.b64 {%0, %1}, %2;" : "=f"(r.x), "=f"(r.y) : "l"(v)); return r;
}
__device__ __forceinline__ void fma2(unsigned long long& d, unsigned long long a, unsigned long long b) {
    asm("fma.rn.f32x2 %0, %1, %2, %0;" : "+l"(d) : "l"(a), "l"(b));
}
__device__ __forceinline__ float sigf(float x)   { return 1.f / (1.f + __expf(-x)); }
__device__ __forceinline__ float tanhf_(float x) { return 2.f / (1.f + __expf(-2.f * x)) - 1.f; }
__device__ __forceinline__ float actf(float x)   { return x > 0.f ? 1.f / (1.f + __expf(-x)) : 0.5f; }

__device__ __forceinline__ unsigned short bf16hi(float v) {
    __nv_bfloat16 h = __float2bfloat16(v);
    return *(unsigned short*)&h;
}
__device__ __forceinline__ float bf16val(unsigned short u) {
    __nv_bfloat16 h = *(__nv_bfloat16*)&u;
    return __bfloat162float(h);
}

__device__ __forceinline__ void mma16816(float* d, const unsigned* a, unsigned b0, unsigned b1) {
    asm volatile("mma.sync.aligned.m16n8k16.row.col.f32.bf16.bf16.f32 "
                 "{%0,%1,%2,%3}, {%4,%5,%6,%7}, {%8,%9}, {%0,%1,%2,%3};"
                 : "+f"(d[0]), "+f"(d[1]), "+f"(d[2]), "+f"(d[3])
                 : "r"(a[0]), "r"(a[1]), "r"(a[2]), "r"(a[3]), "r"(b0), "r"(b1));
}

// ---------------- input GEMM (FFMA2) ----------------
template<int KDIM, int MODEB>
__global__ void __launch_bounds__(256)
gemm_gx_kernel(const float* __restrict__ W, const float* __restrict__ X,
               const float* __restrict__ bA, const float* __restrict__ bB,
               float* __restrict__ gx)
{
    __shared__ float As[16][132];
    __shared__ float Bs[16][68];
    const int s  = blockIdx.y, gt = blockIdx.x, t = threadIdx.x;
    const int tx = t & 15, ty = t >> 4;
    const int b0 = tx * 4, g0 = ty * 8;
    unsigned long long acc[8][2];
#pragma unroll
    for (int i = 0; i < 8; ++i) { acc[i][0] = 0ull; acc[i][1] = 0ull; }
    const int rA = t >> 1, cA = (t & 1) * 8;

    for (int kt = 0; kt < KDIM / 16; ++kt) {
        {
            const float* src = W + (size_t)(gt * 128 + rA) * KDIM + kt * 16 + cA;
            float4 a0 = *(const float4*)src;
            float4 a1 = *(const float4*)(src + 4);
            As[cA + 0][rA] = a0.x; As[cA + 1][rA] = a0.y; As[cA + 2][rA] = a0.z; As[cA + 3][rA] = a0.w;
            As[cA + 4][rA] = a1.x; As[cA + 5][rA] = a1.y; As[cA + 6][rA] = a1.z; As[cA + 7][rA] = a1.w;
        }
        if (MODEB == 0) {
            int bb = t >> 2, q = (t & 3) * 4;
            float4 v = *(const float4*)(X + ((size_t)bb * S_ + s) * KDIM + kt * 16 + q);
            Bs[q + 0][bb] = v.x; Bs[q + 1][bb] = v.y; Bs[q + 2][bb] = v.z; Bs[q + 3][bb] = v.w;
        } else {
            int dk = t >> 4, bb = (t & 15) * 4;
            float4 v = *(const float4*)(X + ((size_t)s * KDIM + kt * 16 + dk) * B_ + bb);
            *(float4*)&Bs[dk][bb] = v;
        }
        __syncthreads();
#pragma unroll
        for (int k = 0; k < 16; ++k) {
            float4 a0 = *(const float4*)&As[k][g0];
            float4 a1 = *(const float4*)&As[k][g0 + 4];
            float4 bv = *(const float4*)&Bs[k][b0];
            unsigned long long bp0 = pk2(bv.x, bv.y), bp1 = pk2(bv.z, bv.w), av;
            av = pk2(a0.x, a0.x); fma2(acc[0][0], av, bp0); fma2(acc[0][1], av, bp1);
            av = pk2(a0.y, a0.y); fma2(acc[1][0], av, bp0); fma2(acc[1][1], av, bp1);
            av = pk2(a0.z, a0.z); fma2(acc[2][0], av, bp0); fma2(acc[2][1], av, bp1);
            av = pk2(a0.w, a0.w); fma2(acc[3][0], av, bp0); fma2(acc[3][1], av, bp1);
            av = pk2(a1.x, a1.x); fma2(acc[4][0], av, bp0); fma2(acc[4][1], av, bp1);
            av = pk2(a1.y, a1.y); fma2(acc[5][0], av, bp0); fma2(acc[5][1], av, bp1);
            av = pk2(a1.z, a1.z); fma2(acc[6][0], av, bp0); fma2(acc[6][1], av, bp1);
            av = pk2(a1.w, a1.w); fma2(acc[7][0], av, bp0); fma2(acc[7][1], av, bp1);
        }
        __syncthreads();
    }
#pragma unroll
    for (int gi = 0; gi < 8; ++gi) {
        int g = gt * 128 + g0 + gi;
        float bias = bA[g] + bB[g];
        float2 p0 = upk2(acc[gi][0]), p1 = upk2(acc[gi][1]);
        *(float4*)(gx + ((size_t)s * G4_ + g) * B_ + b0) =
            make_float4(p0.x + bias, p0.y + bias, p1.x + bias, p1.y + bias);
    }
}

// ---------------- weight prep: pack Whh into per-thread mma A fragments (bf16 hi/lo) ----------------
__global__ void __launch_bounds__(256)
prep_w_kernel(const float* __restrict__ Whh0, const float* __restrict__ Whh1)
{
    unsigned idx  = blockIdx.x * 256 + threadIdx.x;   // 2^20
    unsigned lane = idx & 31;
    unsigned kt   = (idx >> 5) & 7;
    unsigned mt   = (idx >> 8) & 1;
    unsigned w    = (idx >> 9) & 7;
    unsigned cta  = (idx >> 12) & 127;
    unsigned l    = idx >> 19;
    const float* W = l ? Whh1 : Whh0;

    unsigned hi[4], lo[4];
#pragma unroll
    for (int p = 0; p < 4; ++p) {
        unsigned r = (lane >> 2) + (p & 1) * 8;
        unsigned c = (lane & 3) * 2 + (p >> 1) * 8;
        unsigned rloc = mt * 16 + r;
        unsigned gr = cta * 32 + rloc;
        unsigned j = gr >> 2, gate = gr & 3;
        unsigned k = w * 128 + kt * 16 + c;
        float2 v = *(const float2*)(W + ((size_t)(gate * H_ + j)) * H_ + k);
        unsigned short h0 = bf16hi(v.x);
        unsigned short l0 = bf16hi(v.x - bf16val(h0));
        unsigned short h1 = bf16hi(v.y);
        unsigned short l1 = bf16hi(v.y - bf16val(h1));
        hi[p] = (unsigned)h0 | ((unsigned)h1 << 16);
        lo[p] = (unsigned)l0 | ((unsigned)l1 << 16);
    }
    size_t fr = ((((size_t)(l * 128 + cta) * 8 + w) * 2 + mt) * 8 + kt) * 32 + lane;
    uint4* dst = (uint4*)g_WF + fr * 2;
    dst[0] = make_uint4(hi[0], hi[1], hi[2], hi[3]);
    dst[1] = make_uint4(lo[0], lo[1], lo[2], lo[3]);
}

__global__ void reset_flags_kernel() { g_flags[threadIdx.x] = 0; }

// ---------------- mma.sync recurrence: 128 CTAs, M=32 (8j x 4 gates) x N=64, K split over 8 warps ----------------
__global__ void __launch_bounds__(256, 1)
recur_mma_kernel(const float* __restrict__ gx, float* __restrict__ hseq, int layer)
{
    extern __shared__ float Rbuf[];   // [8 warps][32 rows][RSTR] f32

    const int tid  = threadIdx.x;
    const int w    = tid >> 5;
    const int lane = tid & 31;
    const int cta  = blockIdx.x;

    // register-resident A fragments
    unsigned Ah[2][8][4], Al[2][8][4];
    {
        const uint4* wf = (const uint4*)g_WF +
            ((((size_t)(layer * 128 + cta) * 8 + w) * 16) * 32 + lane) * 2;
#pragma unroll
        for (int mt = 0; mt < 2; ++mt)
#pragma unroll
            for (int kt = 0; kt < 8; ++kt) {
                const uint4* p = wf + (size_t)(mt * 8 + kt) * 64;
                uint4 h = p[0], lv = p[1];
                Ah[mt][kt][0] = h.x;  Ah[mt][kt][1] = h.y;  Ah[mt][kt][2] = h.z;  Ah[mt][kt][3] = h.w;
                Al[mt][kt][0] = lv.x; Al[mt][kt][1] = lv.y; Al[mt][kt][2] = lv.z; Al[mt][kt][3] = lv.w;
            }
    }

    const int n   = tid & 63;
    const int jl0 = tid >> 6;          // 0..3
    float cs0 = 0.f, cs1 = 0.f;

    volatile int* vf = (volatile int*)g_flags;

    for (int t = 0; t < S_; ++t) {
        if (t > 0) {
            if (tid == 0) { while (vf[t - 1] != NCTA) {} }
            __syncthreads();
            __threadfence();

            float acc[2][8][4];
#pragma unroll
            for (int mt = 0; mt < 2; ++mt)
#pragma unroll
                for (int nt = 0; nt < 8; ++nt)
#pragma unroll
                    for (int q = 0; q < 4; ++q) acc[mt][nt][q] = 0.f;

            const uint4* hb = (const uint4*)g_hfrag + (size_t)((t - 1) & 1) * 16384;
#pragma unroll
            for (int kt = 0; kt < 8; ++kt) {
                const uint4* kb = hb + ((size_t)(w * 8 + kt) * 8) * 32 + lane;
#pragma unroll
                for (int nt = 0; nt < 8; ++nt) {
                    uint4 Bv = kb[nt * 32];
                    mma16816(acc[0][nt], Ah[0][kt], Bv.x, Bv.y);
                    mma16816(acc[1][nt], Ah[1][kt], Bv.x, Bv.y);
                    mma16816(acc[0][nt], Al[0][kt], Bv.x, Bv.y);
                    mma16816(acc[1][nt], Al[1][kt], Bv.x, Bv.y);
                    mma16816(acc[0][nt], Ah[0][kt], Bv.z, Bv.w);
                    mma16816(acc[1][nt], Ah[1][kt], Bv.z, Bv.w);
                }
            }

            // store k-partials to smem (stride RSTR=66 floats -> all float2 8B-aligned)
            {
                const int r0 = lane >> 2;
                const int c0 = (lane & 3) * 2;
#pragma unroll
                for (int mt = 0; mt < 2; ++mt)
#pragma unroll
                    for (int nt = 0; nt < 8; ++nt) {
                        float* dst = Rbuf + ((size_t)w * 32 + mt * 16 + r0) * RSTR + nt * 8 + c0;
                        *(float2*)dst = make_float2(acc[mt][nt][0], acc[mt][nt][1]);
                        *(float2*)(dst + 8 * RSTR) = make_float2(acc[mt][nt][2], acc[mt][nt][3]);
                    }
            }
        }
        __syncthreads();

        // ---------------- reduction + epilogue (2 cells per thread) ----------------
        unsigned char* hfd = g_hfrag + (size_t)(t & 1) * 262144;
#pragma unroll
        for (int ci = 0; ci < 2; ++ci) {
            int jloc = jl0 + ci * 4;
            int j = cta * 8 + jloc;
            const float* gp = gx + ((size_t)t * G4_ + j) * B_ + n;
            float pi = gp[0];
            float pf = gp[(size_t)1 * H_ * B_];
            float pg = gp[(size_t)2 * H_ * B_];
            float po = gp[(size_t)3 * H_ * B_];
            if (t > 0) {
#pragma unroll
                for (int w8 = 0; w8 < 8; ++w8) {
                    const float* rp = Rbuf + ((size_t)w8 * 32 + jloc * 4) * RSTR + n;
                    pi += rp[0];
                    pf += rp[RSTR];
                    pg += rp[2 * RSTR];
                    po += rp[3 * RSTR];
                }
            }
            float iv = sigf(pi), fv = sigf(pf), gv = tanhf_(pg), ov = sigf(po);
            float& cs = ci ? cs1 : cs0;
            cs = fv * cs + iv * gv;
            float h = ov * tanhf_(cs);
            hseq[((size_t)t * H_ + j) * B_ + n] = h;

            unsigned short hh = bf16hi(h);
            unsigned short hl = bf16hi(h - bf16val(hh));
            int ktile = j >> 4, kk = j & 15;
            int ntile = n >> 3, nn = n & 7;
            int flane = nn * 4 + ((kk & 7) >> 1);
            size_t byte = (((size_t)ktile * 8 + ntile) * 32 + flane) * 16 + (kk >> 3) * 4 + (kk & 1) * 2;
            *(unsigned short*)(hfd + byte)     = hh;
            *(unsigned short*)(hfd + byte + 8) = hl;
        }

        __threadfence();
        __syncthreads();
        if (tid == 0) atomicAdd(&g_flags[t], 1);
    }
}

// ---------------- fused transpose + sigmoid(relu) ----------------
__global__ void __launch_bounds__(256)
act_out_kernel(const float* __restrict__ h2, float* __restrict__ out)
{
    __shared__ float T[64][68];
    const int s = blockIdx.y, jt = blockIdx.x, t = threadIdx.x;
    {
        int jj0 = (t >> 4) * 4, bq = (t & 15) * 4;
#pragma unroll
        for (int r = 0; r < 4; ++r)
            *(float4*)&T[jj0 + r][bq] =
                *(const float4*)(h2 + ((size_t)s * H_ + jt * 64 + jj0 + r) * B_ + bq);
    }
    __syncthreads();
    {
        int b0 = (t >> 4) * 4, jq = (t & 15) * 4;
#pragma unroll
        for (int i = 0; i < 4; ++i) {
            int b = b0 + i;
            float4 w;
            w.x = actf(T[jq + 0][b]); w.y = actf(T[jq + 1][b]);
            w.z = actf(T[jq + 2][b]); w.w = actf(T[jq + 3][b]);
            *(float4*)(out + (size_t)b * (S_ * H_) + (size_t)s * H_ + jt * 64 + jq) = w;
        }
    }
}

// ---------------- launcher ----------------
extern "C" void kernel_launch(void* const* d_in, const int* in_sizes, int n_in,
                              void* d_out, int out_size)
{
    const float* x    = (const float*)d_in[0];
    const float* Wih0 = (const float*)d_in[1];
    const float* Whh0 = (const float*)d_in[2];
    const float* bih0 = (const float*)d_in[3];
    const float* bhh0 = (const float*)d_in[4];
    const float* Wih1 = (const float*)d_in[5];
    const float* Whh1 = (const float*)d_in[6];
    const float* bih1 = (const float*)d_in[7];
    const float* bhh1 = (const float*)d_in[8];
    float* out = (float*)d_out;

    float *gx, *h1, *h2;
    cudaGetSymbolAddress((void**)&gx, g_gx);
    cudaGetSymbolAddress((void**)&h1, g_h1);
    cudaGetSymbolAddress((void**)&h2, g_h2);

    const int smem_rec = 8 * 32 * RSTR * (int)sizeof(float);   // 67584
    cudaFuncSetAttribute(recur_mma_kernel, cudaFuncAttributeMaxDynamicSharedMemorySize, smem_rec);

    dim3 ggrid(G4_ / 128, S_);

    prep_w_kernel<<<4096, 256>>>(Whh0, Whh1);

    gemm_gx_kernel<D_, 0><<<ggrid, 256>>>(Wih0, x, bih0, bhh0, gx);
    reset_flags_kernel<<<1, 256>>>();
    recur_mma_kernel<<<NCTA, 256, smem_rec>>>(gx, h1, 0);

    gemm_gx_kernel<H_, 1><<<ggrid, 256>>>(Wih1, h1, bih1, bhh1, gx);
    reset_flags_kernel<<<1, 256>>>();
    recur_mma_kernel<<<NCTA, 256, smem_rec>>>(gx, h2, 1);

    dim3 agrid(H_ / 64, S_);
    act_out_kernel<<<agrid, 256>>>(h2, out);
}